// round 14
// baseline (speedup 1.0000x reference)
#include <cuda.h>
#include <cuda_runtime.h>
#include <cuda_bf16.h>
#include <cstdint>

// loss = mean_{i!=j} (cos(q_i,q_j) - cos(k_i,k_j))^2
// Sq_ij - Sk_ij = [u_i,v_i].[u_j,-v_j]  =>  C = P @ P^T with b_negate on the
// v-half K-chunks (idesc bit 14). tcgen05 path (single fused kernel):
//   phase 1: 136 CTAs row-normalize fq/fk -> bf16 g_P (warp-per-row loop),
//            TMEM alloc + barrier init hoisted to overlap
//   grid-wide arrival-counter barrier (all CTAs co-resident, one wave)
//   phase 2: per-CTA TMA pipeline, warp-specialized producer(t32)/consumer(t0)
//   epilogue: square-sum strict upper triangle (x2), finalize in last CTA.
// Host dispatches on runtime CC; fallback path = separate norm + FFMA2 GEMM.

#if defined(__CUDA_ARCH_FEAT_SM100_ALL) || defined(__CUDA_ARCH_FEAT_SM103_ALL) || \
    (defined(__CUDA_ARCH_SPECIFIC__) && (__CUDA_ARCH_SPECIFIC__ >= 1000) && (__CUDA_ARCH_SPECIFIC__ < 1100))
#define HAS_TC 1
#else
#define HAS_TC 0
#endif

#define NROWS 4096
#define DDIM  1024
#define KTOT  2048

// ---- tcgen05 tile config: 256x256 tile per CTA (2 x M128/N256 MMA) ----
#define BM 256
#define BN 256
#define KC 64                       // bf16 elems per chunk (128 B per row)
#define NCHUNK (KTOT / KC)          // 32
#define NEGCHUNK (DDIM / KC)        // 16
#define NSTAGE 3
#define NT  (NROWS / 256)           // 16
#define NTILES_TC 136               // triangle tj >= ti of 16x16

#define A_STAGE_BYTES (BM * 128)    // 32768
#define B_STAGE_BYTES (BN * 128)    // 32768
#define STAGE_BYTES   (A_STAGE_BYTES + B_STAGE_BYTES)   // 65536
#define SMEM_HDR      1024
#define SMEM_DYN      (1024 + SMEM_HDR + NSTAGE * STAGE_BYTES)

// idesc: F32 acc, BF16 a/b, N=256, M=128, K-major; bit14 = b_negate
#define MMA_IDESC ((1u<<4) | (1u<<7) | (1u<<10) | ((256u/8u)<<17) | ((128u/16u)<<24))
#define MMA_IDESC_NEGB (MMA_IDESC | (1u<<14))

// ---- FFMA fallback tile config ----
#define FBM 128
#define FBK 16
#define LDSS 132
#define NTILES_FF 528

__device__ __nv_bfloat16 g_P[(size_t)NROWS * KTOT];  // [u, v] (unit rows)
__device__ double g_acc;
__device__ unsigned int g_count;    // finalize arrival counter
__device__ unsigned int g_sync;     // phase-1 grid barrier counter

// ---------------------------------------------------------------------------
// Arch-neutral helpers
// ---------------------------------------------------------------------------
__device__ __forceinline__ uint32_t smem_u32(const void* p) {
    uint32_t a;
    asm("{ .reg .u64 t; cvta.to.shared.u64 t, %1; cvt.u32.u64 %0, t; }"
        : "=r"(a) : "l"(p));
    return a;
}

#define MBAR_INIT(a, n) \
    asm volatile("mbarrier.init.shared.b64 [%0], %1;" :: "r"(a), "r"(n) : "memory")
#define MBAR_INVAL(a) \
    asm volatile("mbarrier.inval.shared.b64 [%0];" :: "r"(a) : "memory")
#define MBAR_EXPECT_TX(a, tx) \
    asm volatile("mbarrier.arrive.expect_tx.shared.b64 _, [%0], %1;" \
                 :: "r"(a), "r"(tx) : "memory")
#define MBAR_WAIT(a, p) do { \
    uint32_t _m = (a); uint32_t _p = (p); uint32_t _d; \
    asm volatile("{\n\t.reg .pred q;\n\t" \
        "mbarrier.try_wait.parity.acquire.cta.shared::cta.b64 q, [%1], %2;\n\t" \
        "selp.b32 %0, 1, 0, q;\n\t}" : "=r"(_d) : "r"(_m), "r"(_p) : "memory"); \
    if (!_d) { \
        asm volatile("{\n\t.reg .pred Q1;\n\tWL_%=:\n\t" \
            "mbarrier.try_wait.parity.acquire.cta.shared::cta.b64 Q1, [%0], %1, 0x989680;\n\t" \
            "@Q1 bra.uni WD_%=;\n\tbra.uni WL_%=;\n\tWD_%=:\n\t}" \
            :: "r"(_m), "r"(_p) : "memory"); \
    } } while (0)

// finalize fused into last CTA; also resets phase-1 barrier for graph replay
__device__ __forceinline__ void block_finalize(int tid, float* out, unsigned ntiles) {
    if (tid == 0) {
        __threadfence();
        unsigned old = atomicAdd(&g_count, 1u);
        if (old == ntiles - 1) {
            double s = atomicAdd(&g_acc, 0.0);
            out[0] = (float)(s / ((double)NROWS * (double)(NROWS - 1)));
            g_acc = 0.0;
            g_count = 0u;
            g_sync = 0u;
            __threadfence();
        }
    }
}

// warp-per-row normalize of one slot (row, which); writes bf16 into g_P
__device__ __forceinline__ void norm_slot(int slot, int lane,
                                          const float* __restrict__ fq,
                                          const float* __restrict__ fk) {
    int row = slot & (NROWS - 1);
    int which = slot >> 12;
    const float* src = (which ? fk : fq) + (size_t)row * DDIM;

    float4 v[8];
#pragma unroll
    for (int i = 0; i < 8; i++)
        v[i] = reinterpret_cast<const float4*>(src)[lane + 32 * i];

    float ss = 0.f;
#pragma unroll
    for (int i = 0; i < 8; i++)
        ss += v[i].x * v[i].x + v[i].y * v[i].y + v[i].z * v[i].z + v[i].w * v[i].w;
#pragma unroll
    for (int o = 16; o; o >>= 1) ss += __shfl_xor_sync(0xffffffffu, ss, o);

    float inv = rsqrtf(ss);
    size_t base = (size_t)row * KTOT + (size_t)which * DDIM;
#pragma unroll
    for (int i = 0; i < 8; i++) {
        union { uint2 u; __nv_bfloat162 b[2]; } wq;
        wq.b[0] = __floats2bfloat162_rn(v[i].x * inv, v[i].y * inv);
        wq.b[1] = __floats2bfloat162_rn(v[i].z * inv, v[i].w * inv);
        *reinterpret_cast<uint2*>(&g_P[base + (size_t)(lane + 32 * i) * 4]) = wq.u;
    }
}

// ---------------------------------------------------------------------------
// Kernel 1 (fallback path only): standalone normalize
// ---------------------------------------------------------------------------
__global__ __launch_bounds__(256) void norm_kernel(const float* __restrict__ fq,
                                                   const float* __restrict__ fk) {
    int t = threadIdx.x;
    norm_slot(blockIdx.x * 8 + (t >> 5), t & 31, fq, fk);
    if (blockIdx.x == 0 && t == 0) g_acc = 0.0;
}

// ---------------------------------------------------------------------------
// tcgen05-only helpers
// ---------------------------------------------------------------------------
#if HAS_TC
#define TC_ALLOC(sa, n) \
    asm volatile("tcgen05.alloc.cta_group::1.sync.aligned.shared::cta.b32 [%0], %1;" \
                 :: "r"(sa), "r"(n) : "memory")
#define TC_RELINQ() \
    asm volatile("tcgen05.relinquish_alloc_permit.cta_group::1.sync.aligned;")
#define TC_DEALLOC(t, n) \
    asm volatile("tcgen05.dealloc.cta_group::1.sync.aligned.b32 %0, %1;" :: "r"(t), "r"(n))
#define TC_COMMIT(mb) \
    asm volatile("tcgen05.commit.cta_group::1.mbarrier::arrive::one.shared::cluster.b64 [%0];" \
                 :: "r"(mb) : "memory")
#define TC_FENCE_AFTER() asm volatile("tcgen05.fence::after_thread_sync;" ::: "memory")
#define TC_FENCE_BEFORE() asm volatile("tcgen05.fence::before_thread_sync;" ::: "memory")
#define TC_WAIT_LD() asm volatile("tcgen05.wait::ld.sync.aligned;" ::: "memory")

#define TMA2D(smem, tmap_p, x, y, mbar) \
    asm volatile( \
        "cp.async.bulk.tensor.2d.shared::cta.global.tile.mbarrier::complete_tx::bytes " \
        "[%0], [%1, {%2, %3}], [%4];" \
        :: "r"(smem), "l"(tmap_p), "r"(x), "r"(y), "r"(mbar) : "memory")

// SW128 K-major SMEM descriptor (LBO=1, SBO=64, version=1)
__device__ __forceinline__ uint64_t make_desc(uint32_t addr) {
    return (uint64_t(2) << 61) | (uint64_t(1) << 46) | (uint64_t(64) << 32)
         | (uint64_t(1) << 16) | ((uint64_t)(addr >> 4) & 0x3FFF);
}

__device__ __forceinline__ void mma_f16_ss(uint32_t d, uint64_t a, uint64_t b,
                                           uint32_t idesc, uint32_t enable) {
    asm volatile(
        "{\n\t.reg .pred p;\n\tsetp.ne.u32 p, %5, 0;\n\t"
        "tcgen05.mma.cta_group::1.kind::f16 [%0], %1, %2, %3, {%4,%4,%4,%4}, p;\n\t}"
        :: "r"(d), "l"(a), "l"(b), "r"(idesc), "r"(0u), "r"(enable) : "memory");
}

#define TC_LD_X32(r, ta) \
    asm volatile( \
        "tcgen05.ld.sync.aligned.32x32b.x32.b32 " \
        "{%0,%1,%2,%3,%4,%5,%6,%7,%8,%9,%10,%11,%12,%13,%14,%15," \
        "%16,%17,%18,%19,%20,%21,%22,%23,%24,%25,%26,%27,%28,%29,%30,%31}, [%32];" \
        : "=r"((r)[0]),"=r"((r)[1]),"=r"((r)[2]),"=r"((r)[3]), \
          "=r"((r)[4]),"=r"((r)[5]),"=r"((r)[6]),"=r"((r)[7]), \
          "=r"((r)[8]),"=r"((r)[9]),"=r"((r)[10]),"=r"((r)[11]), \
          "=r"((r)[12]),"=r"((r)[13]),"=r"((r)[14]),"=r"((r)[15]), \
          "=r"((r)[16]),"=r"((r)[17]),"=r"((r)[18]),"=r"((r)[19]), \
          "=r"((r)[20]),"=r"((r)[21]),"=r"((r)[22]),"=r"((r)[23]), \
          "=r"((r)[24]),"=r"((r)[25]),"=r"((r)[26]),"=r"((r)[27]), \
          "=r"((r)[28]),"=r"((r)[29]),"=r"((r)[30]),"=r"((r)[31]) \
        : "r"(ta))
#endif  // HAS_TC

// ---------------------------------------------------------------------------
// Kernel 2a: FUSED norm + grid barrier + tcgen05 256x256 triangle GEMM
// ---------------------------------------------------------------------------
__global__ __launch_bounds__(256, 1)
void gemm_tc(float* out, const __grid_constant__ CUtensorMap tmap,
             const float* __restrict__ fq, const float* __restrict__ fk) {
#if HAS_TC
    extern __shared__ __align__(16) char smem[];
    uint32_t smem_base = (smem_u32(smem) + 1023u) & ~1023u;
    int tid = threadIdx.x;
    int wid = tid >> 5;
    int lid = tid & 31;

    // block -> (ti, tj) over triangle tj >= ti of 16x16 256-tiles
    int b = blockIdx.x;
    int ti = 0;
    while (b >= (NT - ti)) { b -= (NT - ti); ti++; }
    int tj = ti + b;

    // header: [0] tmem ptr; full[3]@8; mma[3]@32; final@56
    uint32_t full0 = smem_base + 8, mma0 = smem_base + 32, finmb = smem_base + 56;

    // ---- prologue setup (overlaps with phase-1 norm work) ----
    if (wid == 0) TC_ALLOC(smem_base, 512);
    if (tid == 0) {
#pragma unroll
        for (int s = 0; s < NSTAGE; s++) {
            MBAR_INIT(full0 + 8 * s, 1);
            MBAR_INIT(mma0 + 8 * s, 1);
        }
        MBAR_INIT(finmb, 1);
        if (blockIdx.x == 0) g_acc = 0.0;
    }

    // ---- phase 1: normalize (warp-per-row, strided over 8192 slots) ----
    for (int slot = blockIdx.x * 8 + wid; slot < 2 * NROWS; slot += NTILES_TC * 8)
        norm_slot(slot, lid, fq, fk);

    // ---- grid-wide barrier: all g_P writes visible before any TMA ----
    __threadfence();
    __syncthreads();
    if (tid == 0) {
        atomicAdd(&g_sync, 1u);
        while (atomicAdd(&g_sync, 0u) < NTILES_TC) { }
        __threadfence();
    }
    __syncthreads();

    uint32_t tmem;
    asm volatile("ld.shared.b32 %0, [%1];" : "=r"(tmem) : "r"(smem_base));

    uint32_t stA[NSTAGE], stB[NSTAGE];
#pragma unroll
    for (int s = 0; s < NSTAGE; s++) {
        stA[s] = smem_base + SMEM_HDR + s * STAGE_BYTES;
        stB[s] = stA[s] + A_STAGE_BYTES;
    }

    const CUtensorMap* tm = &tmap;
    int rowA = ti * BM;
    int rowB = tj * BN;

    if (tid == 32) {
        // ---- producer (TMA issue) ----
        for (int pre = 0; pre < NCHUNK; pre++) {
            int sp = pre % NSTAGE;
            if (pre >= NSTAGE)   // stage free once chunk pre-NSTAGE's MMA retired
                MBAR_WAIT(mma0 + 8 * sp, ((pre / NSTAGE) - 1) & 1);
            MBAR_EXPECT_TX(full0 + 8 * sp, STAGE_BYTES);
            TMA2D(stA[sp], tm, pre * KC, rowA, full0 + 8 * sp);
            TMA2D(stB[sp], tm, pre * KC, rowB, full0 + 8 * sp);
        }
    } else if (tid == 0) {
        // ---- consumer (MMA issue) ----
        for (int c = 0; c < NCHUNK; c++) {
            int st = c % NSTAGE;
            MBAR_WAIT(full0 + 8 * st, (c / NSTAGE) & 1);

            uint64_t ad  = make_desc(stA[st]);
            uint64_t ad2 = make_desc(stA[st] + 16384);
            uint64_t bd  = make_desc(stB[st]);
            uint32_t idesc = (c >= NEGCHUNK) ? MMA_IDESC_NEGB : MMA_IDESC;
#pragma unroll
            for (int k = 0; k < 4; k++) {
                uint32_t e = (c > 0 || k > 0) ? 1u : 0u;
                mma_f16_ss(tmem,       ad  + 2 * k, bd + 2 * k, idesc, e);
                mma_f16_ss(tmem + 256, ad2 + 2 * k, bd + 2 * k, idesc, e);
            }
            if (c == NCHUNK - 1) TC_COMMIT(finmb);
            else                 TC_COMMIT(mma0 + 8 * st);
        }
    }

    // all threads: one-shot final MMA barrier (unambiguous phase 0)
    MBAR_WAIT(finmb, 0);
    TC_FENCE_AFTER();

    // epilogue: warps 0-3 -> rows 0..127, warps 4-7 -> rows 128..255
    __shared__ float red[8];
    {
        int half = wid >> 2;
        uint32_t dbase = tmem + half * 256;
        int i = ti * BM + half * 128 + (wid & 3) * 32 + lid;
        float lsum = 0.f;
#pragma unroll
        for (int cb = 0; cb < 8; cb++) {
            uint32_t r[32];
            TC_LD_X32(r, dbase + cb * 32);
            TC_WAIT_LD();
            int jb = tj * BN + cb * 32;
#pragma unroll
            for (int cc = 0; cc < 32; cc++) {
                if (jb + cc > i) {
                    float f = __uint_as_float(r[cc]);
                    lsum += f * f;
                }
            }
        }
        lsum *= 2.f;
#pragma unroll
        for (int o = 16; o; o >>= 1) lsum += __shfl_xor_sync(0xffffffffu, lsum, o);
        if (lid == 0) red[wid] = lsum;
    }
    TC_FENCE_BEFORE();
    __syncthreads();
    if (tid == 0) {
        double s = 0.0;
#pragma unroll
        for (int w = 0; w < 8; w++) s += (double)red[w];
        atomicAdd(&g_acc, s);
#pragma unroll
        for (int st = 0; st < NSTAGE; st++) {
            MBAR_INVAL(full0 + 8 * st);
            MBAR_INVAL(mma0 + 8 * st);
        }
        MBAR_INVAL(finmb);
    }
    __syncthreads();
    if (wid == 0) {
        TC_RELINQ();
        TC_DEALLOC(tmem, 512);
    }
    block_finalize(tid, out, NTILES_TC);
#endif  // HAS_TC
}

// ---------------------------------------------------------------------------
// FFMA2 helpers + fallback GEMM (base-target builds only)
// ---------------------------------------------------------------------------
__device__ __forceinline__ unsigned long long pack_dup(float a) {
    unsigned long long r;
    asm("mov.b64 %0, {%1, %1};" : "=l"(r) : "f"(a));
    return r;
}
__device__ __forceinline__ void ffma2(unsigned long long& d,
                                      unsigned long long a,
                                      unsigned long long b) {
    asm("fma.rn.f32x2 %0, %1, %2, %0;" : "+l"(d) : "l"(a), "l"(b));
}

__global__ __launch_bounds__(256) void gemm_ffma(float* out) {
#if !HAS_TC
    int b = blockIdx.x;
    int ti = 0;
    while (b >= (32 - ti)) { b -= (32 - ti); ti++; }
    int tj = ti + b;

    __shared__ __align__(16) float As[FBK][LDSS];
    __shared__ __align__(16) float Bs[FBK][LDSS];
    __shared__ float red[8];

    int tid = threadIdx.x;
    int tx = tid & 15;
    int ty = tid >> 4;

    const __nv_bfloat16* Abase = g_P + (size_t)ti * FBM * KTOT;
    const __nv_bfloat16* Bbase = g_P + (size_t)tj * FBM * KTOT;

    int l_row = tid >> 1;
    int l_k8  = (tid & 1) * 8;

    unsigned long long acc[8][4];
#pragma unroll
    for (int r = 0; r < 8; r++)
#pragma unroll
        for (int c = 0; c < 4; c++) acc[r][c] = 0ull;

    uint4 ra = *reinterpret_cast<const uint4*>(
        reinterpret_cast<const char*>(Abase) + (size_t)(l_row * KTOT + l_k8) * 2);
    uint4 rb = *reinterpret_cast<const uint4*>(
        reinterpret_cast<const char*>(Bbase) + (size_t)(l_row * KTOT + l_k8) * 2);

    for (int kb = 0; kb < KTOT; kb += FBK) {
        float sgn = (kb >= DDIM) ? -1.0f : 1.0f;
        union { uint4 u; __nv_bfloat162 h[4]; } wa, wb;
        wa.u = ra; wb.u = rb;
#pragma unroll
        for (int j = 0; j < 4; j++) {
            float2 fa = __bfloat1622float2(wa.h[j]);
            float2 fb = __bfloat1622float2(wb.h[j]);
            As[l_k8 + 2 * j][l_row]     = fa.x;
            As[l_k8 + 2 * j + 1][l_row] = fa.y;
            Bs[l_k8 + 2 * j][l_row]     = sgn * fb.x;
            Bs[l_k8 + 2 * j + 1][l_row] = sgn * fb.y;
        }
        __syncthreads();

        if (kb + FBK < KTOT) {
            int kn = kb + FBK;
            ra = *reinterpret_cast<const uint4*>(
                reinterpret_cast<const char*>(Abase) + (size_t)(l_row * KTOT + kn + l_k8) * 2);
            rb = *reinterpret_cast<const uint4*>(
                reinterpret_cast<const char*>(Bbase) + (size_t)(l_row * KTOT + kn + l_k8) * 2);
        }

#pragma unroll
        for (int kk = 0; kk < FBK; kk++) {
            float a[8];
            *reinterpret_cast<float4*>(&a[0]) =
                *reinterpret_cast<const float4*>(&As[kk][ty * 8]);
            *reinterpret_cast<float4*>(&a[4]) =
                *reinterpret_cast<const float4*>(&As[kk][ty * 8 + 4]);
            union { float4 v[2]; unsigned long long u[4]; } bu;
            bu.v[0] = *reinterpret_cast<const float4*>(&Bs[kk][tx * 8]);
            bu.v[1] = *reinterpret_cast<const float4*>(&Bs[kk][tx * 8 + 4]);
#pragma unroll
            for (int r = 0; r < 8; r++) {
                unsigned long long aa = pack_dup(a[r]);
#pragma unroll
                for (int c = 0; c < 4; c++) ffma2(acc[r][c], aa, bu.u[c]);
            }
        }
        __syncthreads();
    }

    int gi0 = ti * FBM + ty * 8;
    int gj0 = tj * FBM + tx * 8;
    float lsum = 0.f;
#pragma unroll
    for (int r = 0; r < 8; r++) {
        int i = gi0 + r;
#pragma unroll
        for (int c = 0; c < 4; c++) {
            union { unsigned long long u; float f[2]; } w;
            w.u = acc[r][c];
            int j0 = gj0 + 2 * c;
            if (j0 > i)     lsum += w.f[0] * w.f[0];
            if (j0 + 1 > i) lsum += w.f[1] * w.f[1];
        }
    }
    lsum *= 2.f;

#pragma unroll
    for (int o = 16; o; o >>= 1) lsum += __shfl_xor_sync(0xffffffffu, lsum, o);
    if ((tid & 31) == 0) red[tid >> 5] = lsum;
    __syncthreads();
    if (tid == 0) {
        double s = 0.0;
#pragma unroll
        for (int w = 0; w < 8; w++) s += (double)red[w];
        atomicAdd(&g_acc, s);
    }
    __syncthreads();
    block_finalize(tid, out, NTILES_FF);
#endif  // !HAS_TC
}

// ---------------------------------------------------------------------------
// Host
// ---------------------------------------------------------------------------
typedef CUresult (*PFN_tmapEncode)(
    CUtensorMap*, CUtensorMapDataType, cuuint32_t, void*,
    const cuuint64_t*, const cuuint64_t*, const cuuint32_t*, const cuuint32_t*,
    CUtensorMapInterleave, CUtensorMapSwizzle, CUtensorMapL2promotion,
    CUtensorMapFloatOOBfill);

static CUtensorMap s_tmap;

extern "C" void kernel_launch(void* const* d_in, const int* in_sizes, int n_in,
                              void* d_out, int out_size) {
    const float* fq = (const float*)d_in[0];
    const float* fk = (const float*)d_in[1];
    (void)in_sizes; (void)n_in; (void)out_size;

    int dev = 0, cc_major = 0;
    cudaGetDevice(&dev);
    cudaDeviceGetAttribute(&cc_major, cudaDevAttrComputeCapabilityMajor, dev);
    bool use_tc = (cc_major == 10);

    if (use_tc) {
        cudaFuncSetAttribute(gemm_tc,
                             cudaFuncAttributeMaxDynamicSharedMemorySize, SMEM_DYN);
        // 2D TMA descriptor for g_P (bf16 [NROWS x KTOT], box 64x256, SW128)
        void* pbase = nullptr;
        cudaGetSymbolAddress(&pbase, g_P);
        void* fn = nullptr;
        cudaDriverEntryPointQueryResult qr;
        cudaGetDriverEntryPointByVersion("cuTensorMapEncodeTiled", &fn, 12000,
                                         cudaEnableDefault, &qr);
        if (fn && pbase) {
            cuuint64_t dims[2]    = {(cuuint64_t)KTOT, (cuuint64_t)NROWS};
            cuuint64_t strides[1] = {(cuuint64_t)KTOT * 2};
            cuuint32_t box[2]     = {KC, 256};
            cuuint32_t es[2]      = {1, 1};
            ((PFN_tmapEncode)fn)(&s_tmap, CU_TENSOR_MAP_DATA_TYPE_BFLOAT16, 2, pbase,
                                 dims, strides, box, es,
                                 CU_TENSOR_MAP_INTERLEAVE_NONE,
                                 CU_TENSOR_MAP_SWIZZLE_128B,
                                 CU_TENSOR_MAP_L2_PROMOTION_L2_128B,
                                 CU_TENSOR_MAP_FLOAT_OOB_FILL_NONE);
        }
        gemm_tc<<<NTILES_TC, 256, SMEM_DYN>>>((float*)d_out, s_tmap, fq, fk);
    } else {
        norm_kernel<<<NROWS / 4, 256>>>(fq, fk);
        gemm_ffma<<<NTILES_FF, 256>>>((float*)d_out);
    }
}

// round 15
// speedup vs baseline: 1.0803x; 1.0803x over previous
#include <cuda.h>
#include <cuda_runtime.h>
#include <cuda_bf16.h>
#include <cstdint>

// loss = mean_{i!=j} (cos(q_i,q_j) - cos(k_i,k_j))^2
// Sq_ij - Sk_ij = [u_i,v_i].[u_j,-v_j]  =>  C = P @ P^T with b_negate on the
// v-half K-chunks (idesc bit 14). tcgen05 path: per-CTA TMA pipeline with
// warp-specialized producer (TMA, thread 32) / consumer (MMA, thread 0).
// PDL: gemm_tc launches programmatically-overlapped with norm; its prologue
// (TMEM alloc + mbarrier init) runs under norm, then grid-dependency sync.
// Epilogue square-sums the strict upper triangle (x2) with an unmasked fast
// path for off-diagonal tiles; finalize fused into the last CTA.

#if defined(__CUDA_ARCH_FEAT_SM100_ALL) || defined(__CUDA_ARCH_FEAT_SM103_ALL) || \
    (defined(__CUDA_ARCH_SPECIFIC__) && (__CUDA_ARCH_SPECIFIC__ >= 1000) && (__CUDA_ARCH_SPECIFIC__ < 1100))
#define HAS_TC 1
#else
#define HAS_TC 0
#endif

#define NROWS 4096
#define DDIM  1024
#define KTOT  2048

// ---- tcgen05 tile config: 256x256 tile per CTA (2 x M128/N256 MMA) ----
#define BM 256
#define BN 256
#define KC 64                       // bf16 elems per chunk (128 B per row)
#define NCHUNK (KTOT / KC)          // 32
#define NEGCHUNK (DDIM / KC)        // 16
#define NSTAGE 3
#define NT  (NROWS / 256)           // 16
#define NTILES_TC 136               // triangle tj >= ti of 16x16

#define A_STAGE_BYTES (BM * 128)    // 32768
#define B_STAGE_BYTES (BN * 128)    // 32768
#define STAGE_BYTES   (A_STAGE_BYTES + B_STAGE_BYTES)   // 65536
#define SMEM_HDR      1024
#define SMEM_DYN      (1024 + SMEM_HDR + NSTAGE * STAGE_BYTES)

// idesc: F32 acc, BF16 a/b, N=256, M=128, K-major; bit14 = b_negate
#define MMA_IDESC ((1u<<4) | (1u<<7) | (1u<<10) | ((256u/8u)<<17) | ((128u/16u)<<24))
#define MMA_IDESC_NEGB (MMA_IDESC | (1u<<14))

// ---- FFMA fallback tile config ----
#define FBM 128
#define FBK 16
#define LDSS 132
#define NTILES_FF 528

__device__ __nv_bfloat16 g_P[(size_t)NROWS * KTOT];  // [u, v] (unit rows)
__device__ double g_acc;
__device__ unsigned int g_count;

// ---------------------------------------------------------------------------
// Arch-neutral helpers
// ---------------------------------------------------------------------------
__device__ __forceinline__ uint32_t smem_u32(const void* p) {
    uint32_t a;
    asm("{ .reg .u64 t; cvta.to.shared.u64 t, %1; cvt.u32.u64 %0, t; }"
        : "=r"(a) : "l"(p));
    return a;
}

#define MBAR_INIT(a, n) \
    asm volatile("mbarrier.init.shared.b64 [%0], %1;" :: "r"(a), "r"(n) : "memory")
#define MBAR_INVAL(a) \
    asm volatile("mbarrier.inval.shared.b64 [%0];" :: "r"(a) : "memory")
#define MBAR_EXPECT_TX(a, tx) \
    asm volatile("mbarrier.arrive.expect_tx.shared.b64 _, [%0], %1;" \
                 :: "r"(a), "r"(tx) : "memory")
#define MBAR_WAIT(a, p) do { \
    uint32_t _m = (a); uint32_t _p = (p); uint32_t _d; \
    asm volatile("{\n\t.reg .pred q;\n\t" \
        "mbarrier.try_wait.parity.acquire.cta.shared::cta.b64 q, [%1], %2;\n\t" \
        "selp.b32 %0, 1, 0, q;\n\t}" : "=r"(_d) : "r"(_m), "r"(_p) : "memory"); \
    if (!_d) { \
        asm volatile("{\n\t.reg .pred Q1;\n\tWL_%=:\n\t" \
            "mbarrier.try_wait.parity.acquire.cta.shared::cta.b64 Q1, [%0], %1, 0x989680;\n\t" \
            "@Q1 bra.uni WD_%=;\n\tbra.uni WL_%=;\n\tWD_%=:\n\t}" \
            :: "r"(_m), "r"(_p) : "memory"); \
    } } while (0)

// finalize fused into last CTA
__device__ __forceinline__ void block_finalize(int tid, float* out, unsigned ntiles) {
    if (tid == 0) {
        __threadfence();
        unsigned old = atomicAdd(&g_count, 1u);
        if (old == ntiles - 1) {
            double s = atomicAdd(&g_acc, 0.0);
            out[0] = (float)(s / ((double)NROWS * (double)(NROWS - 1)));
            g_acc = 0.0;
            g_count = 0u;
            __threadfence();
        }
    }
}

// ---------------------------------------------------------------------------
// Kernel 1: normalize rows -> bf16 P=[u,v]. Warp-per-row, no block syncs.
// ---------------------------------------------------------------------------
__global__ __launch_bounds__(256) void norm_kernel(const float* __restrict__ fq,
                                                   const float* __restrict__ fk) {
    int t = threadIdx.x;
    int w = t >> 5;
    int lane = t & 31;
    int slot = blockIdx.x * 8 + w;
    int row = slot & (NROWS - 1);
    int which = slot >> 12;
    const float* src = (which ? fk : fq) + (size_t)row * DDIM;

    float4 v[8];
#pragma unroll
    for (int i = 0; i < 8; i++)
        v[i] = reinterpret_cast<const float4*>(src)[lane + 32 * i];

    float ss = 0.f;
#pragma unroll
    for (int i = 0; i < 8; i++)
        ss += v[i].x * v[i].x + v[i].y * v[i].y + v[i].z * v[i].z + v[i].w * v[i].w;
#pragma unroll
    for (int o = 16; o; o >>= 1) ss += __shfl_xor_sync(0xffffffffu, ss, o);

    float inv = rsqrtf(ss);

    size_t base = (size_t)row * KTOT + (size_t)which * DDIM;
#pragma unroll
    for (int i = 0; i < 8; i++) {
        union { uint2 u; __nv_bfloat162 b[2]; } wq;
        wq.b[0] = __floats2bfloat162_rn(v[i].x * inv, v[i].y * inv);
        wq.b[1] = __floats2bfloat162_rn(v[i].z * inv, v[i].w * inv);
        *reinterpret_cast<uint2*>(&g_P[base + (size_t)(lane + 32 * i) * 4]) = wq.u;
    }

    if (blockIdx.x == 0 && t == 0) g_acc = 0.0;
}

// ---------------------------------------------------------------------------
// tcgen05-only helpers
// ---------------------------------------------------------------------------
#if HAS_TC
#define TC_ALLOC(sa, n) \
    asm volatile("tcgen05.alloc.cta_group::1.sync.aligned.shared::cta.b32 [%0], %1;" \
                 :: "r"(sa), "r"(n) : "memory")
#define TC_RELINQ() \
    asm volatile("tcgen05.relinquish_alloc_permit.cta_group::1.sync.aligned;")
#define TC_DEALLOC(t, n) \
    asm volatile("tcgen05.dealloc.cta_group::1.sync.aligned.b32 %0, %1;" :: "r"(t), "r"(n))
#define TC_COMMIT(mb) \
    asm volatile("tcgen05.commit.cta_group::1.mbarrier::arrive::one.shared::cluster.b64 [%0];" \
                 :: "r"(mb) : "memory")
#define TC_FENCE_AFTER() asm volatile("tcgen05.fence::after_thread_sync;" ::: "memory")
#define TC_FENCE_BEFORE() asm volatile("tcgen05.fence::before_thread_sync;" ::: "memory")
#define TC_WAIT_LD() asm volatile("tcgen05.wait::ld.sync.aligned;" ::: "memory")

#define TMA2D(smem, tmap_p, x, y, mbar) \
    asm volatile( \
        "cp.async.bulk.tensor.2d.shared::cta.global.tile.mbarrier::complete_tx::bytes " \
        "[%0], [%1, {%2, %3}], [%4];" \
        :: "r"(smem), "l"(tmap_p), "r"(x), "r"(y), "r"(mbar) : "memory")

// SW128 K-major SMEM descriptor (LBO=1, SBO=64, version=1)
__device__ __forceinline__ uint64_t make_desc(uint32_t addr) {
    return (uint64_t(2) << 61) | (uint64_t(1) << 46) | (uint64_t(64) << 32)
         | (uint64_t(1) << 16) | ((uint64_t)(addr >> 4) & 0x3FFF);
}

__device__ __forceinline__ void mma_f16_ss(uint32_t d, uint64_t a, uint64_t b,
                                           uint32_t idesc, uint32_t enable) {
    asm volatile(
        "{\n\t.reg .pred p;\n\tsetp.ne.u32 p, %5, 0;\n\t"
        "tcgen05.mma.cta_group::1.kind::f16 [%0], %1, %2, %3, {%4,%4,%4,%4}, p;\n\t}"
        :: "r"(d), "l"(a), "l"(b), "r"(idesc), "r"(0u), "r"(enable) : "memory");
}

#define TC_LD_X32(r, ta) \
    asm volatile( \
        "tcgen05.ld.sync.aligned.32x32b.x32.b32 " \
        "{%0,%1,%2,%3,%4,%5,%6,%7,%8,%9,%10,%11,%12,%13,%14,%15," \
        "%16,%17,%18,%19,%20,%21,%22,%23,%24,%25,%26,%27,%28,%29,%30,%31}, [%32];" \
        : "=r"((r)[0]),"=r"((r)[1]),"=r"((r)[2]),"=r"((r)[3]), \
          "=r"((r)[4]),"=r"((r)[5]),"=r"((r)[6]),"=r"((r)[7]), \
          "=r"((r)[8]),"=r"((r)[9]),"=r"((r)[10]),"=r"((r)[11]), \
          "=r"((r)[12]),"=r"((r)[13]),"=r"((r)[14]),"=r"((r)[15]), \
          "=r"((r)[16]),"=r"((r)[17]),"=r"((r)[18]),"=r"((r)[19]), \
          "=r"((r)[20]),"=r"((r)[21]),"=r"((r)[22]),"=r"((r)[23]), \
          "=r"((r)[24]),"=r"((r)[25]),"=r"((r)[26]),"=r"((r)[27]), \
          "=r"((r)[28]),"=r"((r)[29]),"=r"((r)[30]),"=r"((r)[31]) \
        : "r"(ta))
#endif  // HAS_TC

// ---------------------------------------------------------------------------
// Kernel 2a: tcgen05 256x256 triangle GEMM, warp-specialized TMA pipeline,
// PDL prologue overlap + fused epilogue + finalize
// ---------------------------------------------------------------------------
__global__ __launch_bounds__(256, 1)
void gemm_tc(float* out, const __grid_constant__ CUtensorMap tmap) {
#if HAS_TC
    extern __shared__ __align__(16) char smem[];
    uint32_t smem_base = (smem_u32(smem) + 1023u) & ~1023u;
    int tid = threadIdx.x;
    int wid = tid >> 5;
    int lid = tid & 31;

    // block -> (ti, tj) over triangle tj >= ti of 16x16 256-tiles
    int b = blockIdx.x;
    int ti = 0;
    while (b >= (NT - ti)) { b -= (NT - ti); ti++; }
    int tj = ti + b;

    // header: [0] tmem ptr; full[3]@8; mma[3]@32; final@56
    uint32_t full0 = smem_base + 8, mma0 = smem_base + 32, finmb = smem_base + 56;

    // ---- norm-independent prologue (overlaps with norm via PDL) ----
    if (wid == 0) TC_ALLOC(smem_base, 512);
    if (tid == 0) {
#pragma unroll
        for (int s = 0; s < NSTAGE; s++) {
            MBAR_INIT(full0 + 8 * s, 1);
            MBAR_INIT(mma0 + 8 * s, 1);
        }
        MBAR_INIT(finmb, 1);
    }
    __syncthreads();
    uint32_t tmem;
    asm volatile("ld.shared.b32 %0, [%1];" : "=r"(tmem) : "r"(smem_base));

    uint32_t stA[NSTAGE], stB[NSTAGE];
#pragma unroll
    for (int s = 0; s < NSTAGE; s++) {
        stA[s] = smem_base + SMEM_HDR + s * STAGE_BYTES;
        stB[s] = stA[s] + A_STAGE_BYTES;
    }

    const CUtensorMap* tm = &tmap;
    int rowA = ti * BM;
    int rowB = tj * BN;

    // ---- wait for norm_kernel to finish before reading g_P ----
    cudaGridDependencySynchronize();

    if (tid == 32) {
        // ---- producer (TMA issue) ----
        for (int pre = 0; pre < NCHUNK; pre++) {
            int sp = pre % NSTAGE;
            if (pre >= NSTAGE)   // stage free once chunk pre-NSTAGE's MMA retired
                MBAR_WAIT(mma0 + 8 * sp, ((pre / NSTAGE) - 1) & 1);
            MBAR_EXPECT_TX(full0 + 8 * sp, STAGE_BYTES);
            TMA2D(stA[sp], tm, pre * KC, rowA, full0 + 8 * sp);
            TMA2D(stB[sp], tm, pre * KC, rowB, full0 + 8 * sp);
        }
    } else if (tid == 0) {
        // ---- consumer (MMA issue) ----
        for (int c = 0; c < NCHUNK; c++) {
            int st = c % NSTAGE;
            MBAR_WAIT(full0 + 8 * st, (c / NSTAGE) & 1);

            uint64_t ad  = make_desc(stA[st]);
            uint64_t ad2 = make_desc(stA[st] + 16384);
            uint64_t bd  = make_desc(stB[st]);
            uint32_t idesc = (c >= NEGCHUNK) ? MMA_IDESC_NEGB : MMA_IDESC;
#pragma unroll
            for (int k = 0; k < 4; k++) {
                uint32_t e = (c > 0 || k > 0) ? 1u : 0u;
                mma_f16_ss(tmem,       ad  + 2 * k, bd + 2 * k, idesc, e);
                mma_f16_ss(tmem + 256, ad2 + 2 * k, bd + 2 * k, idesc, e);
            }
            if (c == NCHUNK - 1) TC_COMMIT(finmb);
            else                 TC_COMMIT(mma0 + 8 * st);
        }
    }

    // all threads: one-shot final MMA barrier (unambiguous phase 0)
    MBAR_WAIT(finmb, 0);
    TC_FENCE_AFTER();

    // epilogue: warps 0-3 -> rows 0..127, warps 4-7 -> rows 128..255
    // off-diagonal tiles (tj > ti): every j > i -> unmasked fast path
    __shared__ float red[8];
    {
        int half = wid >> 2;
        uint32_t dbase = tmem + half * 256;
        int i = ti * BM + half * 128 + (wid & 3) * 32 + lid;
        float lsum = 0.f;
        if (tj > ti) {
#pragma unroll
            for (int cb = 0; cb < 8; cb++) {
                uint32_t r[32];
                TC_LD_X32(r, dbase + cb * 32);
                TC_WAIT_LD();
#pragma unroll
                for (int cc = 0; cc < 32; cc++) {
                    float f = __uint_as_float(r[cc]);
                    lsum += f * f;
                }
            }
        } else {
#pragma unroll
            for (int cb = 0; cb < 8; cb++) {
                uint32_t r[32];
                TC_LD_X32(r, dbase + cb * 32);
                TC_WAIT_LD();
                int jb = tj * BN + cb * 32;
#pragma unroll
                for (int cc = 0; cc < 32; cc++) {
                    if (jb + cc > i) {
                        float f = __uint_as_float(r[cc]);
                        lsum += f * f;
                    }
                }
            }
        }
        lsum *= 2.f;
#pragma unroll
        for (int o = 16; o; o >>= 1) lsum += __shfl_xor_sync(0xffffffffu, lsum, o);
        if (lid == 0) red[wid] = lsum;
    }
    TC_FENCE_BEFORE();
    __syncthreads();
    if (tid == 0) {
        double s = 0.0;
#pragma unroll
        for (int w = 0; w < 8; w++) s += (double)red[w];
        atomicAdd(&g_acc, s);
#pragma unroll
        for (int st = 0; st < NSTAGE; st++) {
            MBAR_INVAL(full0 + 8 * st);
            MBAR_INVAL(mma0 + 8 * st);
        }
        MBAR_INVAL(finmb);
    }
    __syncthreads();
    if (wid == 0) {
        TC_RELINQ();
        TC_DEALLOC(tmem, 512);
    }
    block_finalize(tid, out, NTILES_TC);
#endif  // HAS_TC
}

// ---------------------------------------------------------------------------
// FFMA2 helpers + fallback GEMM (base-target builds only)
// ---------------------------------------------------------------------------
__device__ __forceinline__ unsigned long long pack_dup(float a) {
    unsigned long long r;
    asm("mov.b64 %0, {%1, %1};" : "=l"(r) : "f"(a));
    return r;
}
__device__ __forceinline__ void ffma2(unsigned long long& d,
                                      unsigned long long a,
                                      unsigned long long b) {
    asm("fma.rn.f32x2 %0, %1, %2, %0;" : "+l"(d) : "l"(a), "l"(b));
}

__global__ __launch_bounds__(256) void gemm_ffma(float* out) {
#if !HAS_TC
    int b = blockIdx.x;
    int ti = 0;
    while (b >= (32 - ti)) { b -= (32 - ti); ti++; }
    int tj = ti + b;

    __shared__ __align__(16) float As[FBK][LDSS];
    __shared__ __align__(16) float Bs[FBK][LDSS];
    __shared__ float red[8];

    int tid = threadIdx.x;
    int tx = tid & 15;
    int ty = tid >> 4;

    const __nv_bfloat16* Abase = g_P + (size_t)ti * FBM * KTOT;
    const __nv_bfloat16* Bbase = g_P + (size_t)tj * FBM * KTOT;

    int l_row = tid >> 1;
    int l_k8  = (tid & 1) * 8;

    unsigned long long acc[8][4];
#pragma unroll
    for (int r = 0; r < 8; r++)
#pragma unroll
        for (int c = 0; c < 4; c++) acc[r][c] = 0ull;

    uint4 ra = *reinterpret_cast<const uint4*>(
        reinterpret_cast<const char*>(Abase) + (size_t)(l_row * KTOT + l_k8) * 2);
    uint4 rb = *reinterpret_cast<const uint4*>(
        reinterpret_cast<const char*>(Bbase) + (size_t)(l_row * KTOT + l_k8) * 2);

    for (int kb = 0; kb < KTOT; kb += FBK) {
        float sgn = (kb >= DDIM) ? -1.0f : 1.0f;
        union { uint4 u; __nv_bfloat162 h[4]; } wa, wb;
        wa.u = ra; wb.u = rb;
#pragma unroll
        for (int j = 0; j < 4; j++) {
            float2 fa = __bfloat1622float2(wa.h[j]);
            float2 fb = __bfloat1622float2(wb.h[j]);
            As[l_k8 + 2 * j][l_row]     = fa.x;
            As[l_k8 + 2 * j + 1][l_row] = fa.y;
            Bs[l_k8 + 2 * j][l_row]     = sgn * fb.x;
            Bs[l_k8 + 2 * j + 1][l_row] = sgn * fb.y;
        }
        __syncthreads();

        if (kb + FBK < KTOT) {
            int kn = kb + FBK;
            ra = *reinterpret_cast<const uint4*>(
                reinterpret_cast<const char*>(Abase) + (size_t)(l_row * KTOT + kn + l_k8) * 2);
            rb = *reinterpret_cast<const uint4*>(
                reinterpret_cast<const char*>(Bbase) + (size_t)(l_row * KTOT + kn + l_k8) * 2);
        }

#pragma unroll
        for (int kk = 0; kk < FBK; kk++) {
            float a[8];
            *reinterpret_cast<float4*>(&a[0]) =
                *reinterpret_cast<const float4*>(&As[kk][ty * 8]);
            *reinterpret_cast<float4*>(&a[4]) =
                *reinterpret_cast<const float4*>(&As[kk][ty * 8 + 4]);
            union { float4 v[2]; unsigned long long u[4]; } bu;
            bu.v[0] = *reinterpret_cast<const float4*>(&Bs[kk][tx * 8]);
            bu.v[1] = *reinterpret_cast<const float4*>(&Bs[kk][tx * 8 + 4]);
#pragma unroll
            for (int r = 0; r < 8; r++) {
                unsigned long long aa = pack_dup(a[r]);
#pragma unroll
                for (int c = 0; c < 4; c++) ffma2(acc[r][c], aa, bu.u[c]);
            }
        }
        __syncthreads();
    }

    int gi0 = ti * FBM + ty * 8;
    int gj0 = tj * FBM + tx * 8;
    float lsum = 0.f;
#pragma unroll
    for (int r = 0; r < 8; r++) {
        int i = gi0 + r;
#pragma unroll
        for (int c = 0; c < 4; c++) {
            union { unsigned long long u; float f[2]; } w;
            w.u = acc[r][c];
            int j0 = gj0 + 2 * c;
            if (j0 > i)     lsum += w.f[0] * w.f[0];
            if (j0 + 1 > i) lsum += w.f[1] * w.f[1];
        }
    }
    lsum *= 2.f;

#pragma unroll
    for (int o = 16; o; o >>= 1) lsum += __shfl_xor_sync(0xffffffffu, lsum, o);
    if ((tid & 31) == 0) red[tid >> 5] = lsum;
    __syncthreads();
    if (tid == 0) {
        double s = 0.0;
#pragma unroll
        for (int w = 0; w < 8; w++) s += (double)red[w];
        atomicAdd(&g_acc, s);
    }
    __syncthreads();
    block_finalize(tid, out, NTILES_FF);
#endif  // !HAS_TC
}

// ---------------------------------------------------------------------------
// Host
// ---------------------------------------------------------------------------
typedef CUresult (*PFN_tmapEncode)(
    CUtensorMap*, CUtensorMapDataType, cuuint32_t, void*,
    const cuuint64_t*, const cuuint64_t*, const cuuint32_t*, const cuuint32_t*,
    CUtensorMapInterleave, CUtensorMapSwizzle, CUtensorMapL2promotion,
    CUtensorMapFloatOOBfill);

static CUtensorMap s_tmap;

extern "C" void kernel_launch(void* const* d_in, const int* in_sizes, int n_in,
                              void* d_out, int out_size) {
    const float* fq = (const float*)d_in[0];
    const float* fk = (const float*)d_in[1];
    (void)in_sizes; (void)n_in; (void)out_size;

    int dev = 0, cc_major = 0;
    cudaGetDevice(&dev);
    cudaDeviceGetAttribute(&cc_major, cudaDevAttrComputeCapabilityMajor, dev);
    bool use_tc = (cc_major == 10);

    if (use_tc) {
        cudaFuncSetAttribute(gemm_tc,
                             cudaFuncAttributeMaxDynamicSharedMemorySize, SMEM_DYN);
        void* pbase = nullptr;
        cudaGetSymbolAddress(&pbase, g_P);
        void* fn = nullptr;
        cudaDriverEntryPointQueryResult qr;
        cudaGetDriverEntryPointByVersion("cuTensorMapEncodeTiled", &fn, 12000,
                                         cudaEnableDefault, &qr);
        if (fn && pbase) {
            cuuint64_t dims[2]    = {(cuuint64_t)KTOT, (cuuint64_t)NROWS};
            cuuint64_t strides[1] = {(cuuint64_t)KTOT * 2};
            cuuint32_t box[2]     = {KC, 256};
            cuuint32_t es[2]      = {1, 1};
            ((PFN_tmapEncode)fn)(&s_tmap, CU_TENSOR_MAP_DATA_TYPE_BFLOAT16, 2, pbase,
                                 dims, strides, box, es,
                                 CU_TENSOR_MAP_INTERLEAVE_NONE,
                                 CU_TENSOR_MAP_SWIZZLE_128B,
                                 CU_TENSOR_MAP_L2_PROMOTION_L2_128B,
                                 CU_TENSOR_MAP_FLOAT_OOB_FILL_NONE);
        }

        norm_kernel<<<NROWS / 4, 256>>>(fq, fk);

        // PDL launch: gemm_tc overlaps its prologue with norm_kernel's tail;
        // cudaGridDependencySynchronize() in-kernel gates the g_P reads.
        cudaLaunchConfig_t cfg = {};
        cfg.gridDim = dim3(NTILES_TC, 1, 1);
        cfg.blockDim = dim3(256, 1, 1);
        cfg.dynamicSmemBytes = SMEM_DYN;
        cfg.stream = 0;
        cudaLaunchAttribute attrs[1];
        attrs[0].id = cudaLaunchAttributeProgrammaticStreamSerialization;
        attrs[0].val.programmaticStreamSerializationAllowed = 1;
        cfg.attrs = attrs;
        cfg.numAttrs = 1;
        cudaError_t e = cudaLaunchKernelEx(&cfg, gemm_tc, (float*)d_out, s_tmap);
        if (e != cudaSuccess)   // PDL unsupported -> plain serialized launch
            gemm_tc<<<NTILES_TC, 256, SMEM_DYN>>>((float*)d_out, s_tmap);
    } else {
        norm_kernel<<<NROWS / 4, 256>>>(fq, fk);
        gemm_ffma<<<NTILES_FF, 256>>>((float*)d_out);
    }
}